// round 14
// baseline (speedup 1.0000x reference)
#include <cuda_runtime.h>

#define N_NODES 10000
#define N_EDGES 160000
#define DIM     1280
#define D4      (DIM / 4)     // 320 float4 per row
#define CSLICES 320           // column slices in phase 3
#define SUBROWS 2
#define NTHREADS (CSLICES * SUBROWS)   // 640, 20 warps/block
#define ROWBYTES (DIM * 4)             // 5120 B per node row

// ---- scratch (device globals; zero at load; resets staggered across phases) ----
__device__ float g_outw[N_NODES];
__device__ float g_q[N_NODES];
__device__ float g_Csum;          // sum of all edge weights (C = N + Csum)
__device__ float g_S1[DIM];       // sum_s coef[s]*h0[s]
__device__ float g_msum[DIM];     // sum_s h0[s]
__device__ float g_v1[DIM];       // layer-1 result (atomic-accumulated)

// ---- software grid barrier (nanosleep-paced poll — R10-proven) ----
__device__ unsigned g_cnt = 0;
__device__ volatile unsigned g_gen = 0;

__device__ __forceinline__ void grid_barrier() {
    __syncthreads();
    if (threadIdx.x == 0) {
        __threadfence();
        unsigned gen = g_gen;
        if (atomicAdd(&g_cnt, 1u) == gridDim.x - 1u) {
            g_cnt = 0;
            __threadfence();
            g_gen = gen + 1u;
        } else {
            while (g_gen == gen) { __nanosleep(64); }
        }
        __threadfence();
    }
    __syncthreads();
}

__device__ __forceinline__ void prefetch_l2(const void* p) {
    asm volatile("prefetch.global.L2 [%0];" :: "l"(p));
}

__device__ __forceinline__ float edge_w(float x) {
    return 1.0f / (x * x + 1e-6f);
}
__device__ __forceinline__ void fma4(float4& a, float c, const float4& v) {
    a.x = fmaf(c, v.x, a.x); a.y = fmaf(c, v.y, a.y);
    a.z = fmaf(c, v.z, a.z); a.w = fmaf(c, v.w, a.w);
}
__device__ __forceinline__ void add4(float4& a, const float4& v) {
    a.x += v.x; a.y += v.y; a.z += v.z; a.w += v.w;
}
__device__ __forceinline__ float dot4(const float4& a, const float4& b) {
    return a.x * b.x + a.y * b.y + a.z * b.z + a.w * b.w;
}

__global__ void __launch_bounds__(NTHREADS, 1)
fused_kernel(const float* __restrict__ node,
             const float* __restrict__ ef,
             const int*   __restrict__ src,
             const int*   __restrict__ dst,
             const float* __restrict__ W1,
             const float* __restrict__ b1,
             const float* __restrict__ W2,
             const float* __restrict__ b2,
             float*       __restrict__ out) {
    const int tid = blockIdx.x * blockDim.x + threadIdx.x;
    const int nt  = gridDim.x * blockDim.x;
    const int lane = threadIdx.x & 31;
    const int warp_in_blk = threadIdx.x >> 5;                  // 0..19
    // SM-spread map for matvec phases: consecutive idx land on different SMs
    const int idx  = warp_in_blk * gridDim.x + blockIdx.x;
    const int row_mv  = idx >> 1;                              // 2 warps per row
    const int half_mv = idx & 1;
    const int p3_stride = gridDim.x * SUBROWS;

    __shared__ float sh[32];
    __shared__ float s1sh[DIM];
    __shared__ float mssh[DIM];

    // ---------- Phase 1: outw[src] += ew ; Csum += ew ; resets ; L2 warm ----------
    {
        for (int i = tid; i < DIM; i += nt) {
            g_S1[i] = 0.f; g_msum[i] = 0.f; g_v1[i] = 0.f;
            out[i] = 0.f;                                      // P5 atomics target
        }
        // 2-edge software pipeline
        float csum_local = 0.f;
        {
            int e0 = tid;
            int e1 = tid + nt;
            float f0 = __ldg(&ef[e0]);
            int   u0 = __ldg(&src[e0]);
            float f1 = 0.f; int u1 = 0;
            bool has1 = (e1 < N_EDGES);
            if (has1) { f1 = __ldg(&ef[e1]); u1 = __ldg(&src[e1]); }
            float w0 = edge_w(f0);
            csum_local += w0;
            atomicAdd(&g_outw[u0], w0);
            if (has1) {
                float w1 = edge_w(f1);
                csum_local += w1;
                atomicAdd(&g_outw[u1], w1);
            }
        }
        // ---- L2 warm while atomics drain: W1 + first 8 P3 iterations' rows ----
        {
            long off = (long)tid * 128;
            if (off < (long)DIM * DIM * 4)
                prefetch_l2((const char*)W1 + off);
            int i = threadIdx.x;                                // 0..639
            int row_k = i / 40;                                 // 0..15
            int line  = i % 40;                                 // 0..39 (128B lines/row)
            int s = blockIdx.x * SUBROWS + (row_k & 1) + (row_k >> 1) * p3_stride;
            if (s < N_NODES)
                prefetch_l2((const char*)node + (long)s * ROWBYTES + line * 128);
        }
        #pragma unroll
        for (int o = 16; o; o >>= 1)
            csum_local += __shfl_down_sync(0xffffffffu, csum_local, o);
        if (threadIdx.x < 32) sh[threadIdx.x] = 0.f;
        __syncthreads();
        if (lane == 0) sh[warp_in_blk] = csum_local;
        __syncthreads();
        if (threadIdx.x < 32) {
            float v = sh[threadIdx.x];
            #pragma unroll
            for (int o = 16; o; o >>= 1) v += __shfl_down_sync(0xffffffffu, v, o);
            if (threadIdx.x == 0) atomicAdd(&g_Csum, v);
        }
    }
    grid_barrier();

    // ---------- Phase 2: q[src] += ew*(1+outw[dst]) ; L2 warm W2 + more h0 ----------
    {
        int e0 = tid;
        int e1 = tid + nt;
        float f0 = __ldg(&ef[e0]);
        int   u0 = __ldg(&src[e0]);
        int   d0 = __ldg(&dst[e0]);
        bool has1 = (e1 < N_EDGES);
        float f1 = 0.f; int u1 = 0, d1 = 0;
        if (has1) { f1 = __ldg(&ef[e1]); u1 = __ldg(&src[e1]); d1 = __ldg(&dst[e1]); }
        float ow0 = g_outw[d0];
        float ow1 = has1 ? g_outw[d1] : 0.f;
        float w0 = edge_w(f0);
        float w1 = edge_w(f1);
        atomicAdd(&g_q[u0], w0 * (1.0f + ow0));
        if (has1) atomicAdd(&g_q[u1], w1 * (1.0f + ow1));
        // ---- L2 warm: W2 + next 8 P3 iterations' rows ----
        {
            long off = (long)tid * 128;
            if (off < (long)DIM * DIM * 4)
                prefetch_l2((const char*)W2 + off);
            int i = threadIdx.x;
            int row_k = i / 40;
            int line  = i % 40;
            int s = blockIdx.x * SUBROWS + (row_k & 1) + (8 + (row_k >> 1)) * p3_stride;
            if (s < N_NODES)
                prefetch_l2((const char*)node + (long)s * ROWBYTES + line * 128);
        }
    }
    grid_barrier();

    // ---------- Phase 3: weighted + plain column sums over node_feat0 ----------
    {
        const int sub = threadIdx.x / CSLICES;                 // 0..1
        const int t   = threadIdx.x - sub * CSLICES;           // 0..319
        const int stride = p3_stride;
        const float4* __restrict__ h4 = (const float4*)node;
        float4 aw = make_float4(0.f, 0.f, 0.f, 0.f);
        float4 as = make_float4(0.f, 0.f, 0.f, 0.f);
        int s = blockIdx.x * SUBROWS + sub;
        for (; s + 3 * stride < N_NODES; s += 4 * stride) {
            int s0 = s, s1 = s + stride, s2 = s + 2 * stride, s3 = s + 3 * stride;
            float c0 = 1.0f + __ldg(&g_outw[s0]) + __ldg(&g_q[s0]);
            float c1 = 1.0f + __ldg(&g_outw[s1]) + __ldg(&g_q[s1]);
            float c2 = 1.0f + __ldg(&g_outw[s2]) + __ldg(&g_q[s2]);
            float c3 = 1.0f + __ldg(&g_outw[s3]) + __ldg(&g_q[s3]);
            float4 v0 = __ldg(&h4[(long)s0 * D4 + t]);
            float4 v1 = __ldg(&h4[(long)s1 * D4 + t]);
            float4 v2 = __ldg(&h4[(long)s2 * D4 + t]);
            float4 v3 = __ldg(&h4[(long)s3 * D4 + t]);
            fma4(aw, c0, v0); add4(as, v0);
            fma4(aw, c1, v1); add4(as, v1);
            fma4(aw, c2, v2); add4(as, v2);
            fma4(aw, c3, v3); add4(as, v3);
        }
        for (; s < N_NODES; s += stride) {
            float c = 1.0f + __ldg(&g_outw[s]) + __ldg(&g_q[s]);
            float4 v = __ldg(&h4[(long)s * D4 + t]);
            fma4(aw, c, v); add4(as, v);
        }
        // block-level reduction in shared, then vectorized global flush
        for (int i = threadIdx.x; i < DIM; i += blockDim.x) {
            s1sh[i] = 0.f; mssh[i] = 0.f;
        }
        __syncthreads();
        int d = 4 * t;
        atomicAdd(&s1sh[d + 0], aw.x); atomicAdd(&s1sh[d + 1], aw.y);
        atomicAdd(&s1sh[d + 2], aw.z); atomicAdd(&s1sh[d + 3], aw.w);
        atomicAdd(&mssh[d + 0], as.x); atomicAdd(&mssh[d + 1], as.y);
        atomicAdd(&mssh[d + 2], as.z); atomicAdd(&mssh[d + 3], as.w);
        __syncthreads();
        if (threadIdx.x < CSLICES) {
            float4 v = ((const float4*)s1sh)[threadIdx.x];
            int d2 = 4 * threadIdx.x;
            atomicAdd(&g_S1[d2 + 0], v.x); atomicAdd(&g_S1[d2 + 1], v.y);
            atomicAdd(&g_S1[d2 + 2], v.z); atomicAdd(&g_S1[d2 + 3], v.w);
        } else {
            int j = threadIdx.x - CSLICES;
            float4 v = ((const float4*)mssh)[j];
            int d2 = 4 * j;
            atomicAdd(&g_msum[d2 + 0], v.x); atomicAdd(&g_msum[d2 + 1], v.y);
            atomicAdd(&g_msum[d2 + 2], v.z); atomicAdd(&g_msum[d2 + 3], v.w);
        }
    }
    grid_barrier();

    // ---------- Phase 4: v1 += partial (2 warps/row, W1 L2-hot) ; reset outw/q ----------
    {
        const float invN = 1.0f / (float)N_NODES;
        const float C = (float)N_NODES + g_Csum;
        if (row_mv < DIM) {
            const float4* __restrict__ wr = (const float4*)(W1 + (long)row_mv * DIM);
            const float4* __restrict__ s1 = (const float4*)g_S1;
            const int base = half_mv * (D4 / 2) + lane;        // 160*half + lane
            float acc = 0.f;
            #pragma unroll
            for (int k = 0; k < 5; k++) {
                int j = base + k * 32;
                acc += dot4(__ldg(&wr[j]), s1[j]);
            }
            #pragma unroll
            for (int o = 16; o; o >>= 1) acc += __shfl_down_sync(0xffffffffu, acc, o);
            if (lane == 0) {
                float contrib = acc * invN;
                if (half_mv == 0) contrib += C * invN * __ldg(&b1[row_mv]);
                atomicAdd(&g_v1[row_mv], contrib);
            }
        }
        for (int s2 = tid; s2 < N_NODES; s2 += nt) { g_outw[s2] = 0.f; g_q[s2] = 0.f; }
    }
    grid_barrier();

    // ---------- Phase 5: out += partial + b2 + msum/N (W2 L2-hot) ; reset Csum ----------
    {
        const float invN = 1.0f / (float)N_NODES;
        if (row_mv < DIM) {
            const float4* __restrict__ wr = (const float4*)(W2 + (long)row_mv * DIM);
            const float4* __restrict__ v1 = (const float4*)g_v1;
            const int base = half_mv * (D4 / 2) + lane;
            float acc = 0.f;
            #pragma unroll
            for (int k = 0; k < 5; k++) {
                int j = base + k * 32;
                acc += dot4(__ldg(&wr[j]), v1[j]);
            }
            #pragma unroll
            for (int o = 16; o; o >>= 1) acc += __shfl_down_sync(0xffffffffu, acc, o);
            if (lane == 0) {
                float contrib = acc;
                if (half_mv == 0)
                    contrib += __ldg(&b2[row_mv]) + g_msum[row_mv] * invN;
                atomicAdd(&out[row_mv], contrib);
            }
        }
        if (tid == 0) g_Csum = 0.f;
    }
}

extern "C" void kernel_launch(void* const* d_in, const int* in_sizes, int n_in,
                              void* d_out, int out_size) {
    const float* node = (const float*)d_in[0];   // [N, D]
    const float* ef   = (const float*)d_in[1];   // [E]
    const int*   ei   = (const int*)  d_in[2];   // [2, E]
    const float* W1   = (const float*)d_in[3];
    const float* b1   = (const float*)d_in[4];
    const float* W2   = (const float*)d_in[5];
    const float* b2   = (const float*)d_in[6];
    float* out = (float*)d_out;

    const int* src = ei;
    const int* dst = ei + N_EDGES;

    // Grid barrier safety: exactly 1 block/SM, all simultaneously resident.
    int dev = 0, sms = 148, maxb = 1;
    cudaGetDevice(&dev);
    cudaDeviceGetAttribute(&sms, cudaDevAttrMultiProcessorCount, dev);
    cudaOccupancyMaxActiveBlocksPerMultiprocessor(&maxb, fused_kernel, NTHREADS, 0);
    int grid = (maxb >= 1) ? sms : 1;
    if (grid < 1) grid = 1;

    fused_kernel<<<grid, NTHREADS>>>(node, ef, src, dst, W1, b1, W2, b2, out);
}

// round 15
// speedup vs baseline: 1.1310x; 1.1310x over previous
#include <cuda_runtime.h>

#define N_NODES 10000
#define N_EDGES 160000
#define DIM     1280
#define D4      (DIM / 4)     // 320 float4 per row
#define CSLICES 320
#define SUBROWS 2
#define NTHREADS (CSLICES * SUBROWS)   // 640
#define BANKS   8

// ---- scratch ----
__device__ float g_outw[N_NODES];
__device__ float g_q[N_NODES];
__device__ float g_Csum;
__device__ float g_S1B[BANKS][DIM];    // banked weighted column sums
__device__ float g_msumB[BANKS][DIM];  // banked plain column sums
__device__ float g_v1[DIM];

// ---- software grid barrier ----
__device__ unsigned g_cnt = 0;
__device__ volatile unsigned g_gen = 0;

__device__ __forceinline__ void grid_barrier() {
    __syncthreads();
    if (threadIdx.x == 0) {
        __threadfence();
        unsigned gen = g_gen;
        if (atomicAdd(&g_cnt, 1u) == gridDim.x - 1u) {
            g_cnt = 0;
            __threadfence();
            g_gen = gen + 1u;
        } else {
            while (g_gen == gen) { __nanosleep(64); }
        }
        __threadfence();
    }
    __syncthreads();
}

__device__ __forceinline__ float edge_w(float x) {
    return 1.0f / (x * x + 1e-6f);
}
__device__ __forceinline__ void fma4(float4& a, float c, const float4& v) {
    a.x = fmaf(c, v.x, a.x); a.y = fmaf(c, v.y, a.y);
    a.z = fmaf(c, v.z, a.z); a.w = fmaf(c, v.w, a.w);
}
__device__ __forceinline__ void add4(float4& a, const float4& v) {
    a.x += v.x; a.y += v.y; a.z += v.z; a.w += v.w;
}
__device__ __forceinline__ float dot4(const float4& a, const float4& b) {
    return a.x * b.x + a.y * b.y + a.z * b.z + a.w * b.w;
}

__global__ void __launch_bounds__(NTHREADS, 1)
fused_kernel(const float* __restrict__ node,
             const float* __restrict__ ef,
             const int*   __restrict__ src,
             const int*   __restrict__ dst,
             const float* __restrict__ W1,
             const float* __restrict__ b1,
             const float* __restrict__ W2,
             const float* __restrict__ b2,
             float*       __restrict__ out) {
    const int tid = blockIdx.x * blockDim.x + threadIdx.x;
    const int nt  = gridDim.x * blockDim.x;
    const int lane = threadIdx.x & 31;
    const int warp_in_blk = threadIdx.x >> 5;
    const int idx  = warp_in_blk * gridDim.x + blockIdx.x;     // SM-spread warp id
    const int row_mv  = idx >> 1;
    const int half_mv = idx & 1;

    __shared__ float sh[32];
    __shared__ float s1sh[DIM];
    __shared__ float mssh[DIM];

    // ---------- Phase 1: edges pass 1 + resets ----------
    {
        float* s1b = &g_S1B[0][0];
        float* msb = &g_msumB[0][0];
        for (int i = tid; i < BANKS * DIM; i += nt) { s1b[i] = 0.f; msb[i] = 0.f; }
        for (int i = tid; i < DIM; i += nt) { g_v1[i] = 0.f; out[i] = 0.f; }

        float csum_local = 0.f;
        {
            int e0 = tid, e1 = tid + nt;
            float f0 = __ldg(&ef[e0]);
            int   u0 = __ldg(&src[e0]);
            bool has1 = (e1 < N_EDGES);
            float f1 = 0.f; int u1 = 0;
            if (has1) { f1 = __ldg(&ef[e1]); u1 = __ldg(&src[e1]); }
            float w0 = edge_w(f0);
            csum_local += w0;
            atomicAdd(&g_outw[u0], w0);
            if (has1) {
                float w1 = edge_w(f1);
                csum_local += w1;
                atomicAdd(&g_outw[u1], w1);
            }
        }
        #pragma unroll
        for (int o = 16; o; o >>= 1)
            csum_local += __shfl_down_sync(0xffffffffu, csum_local, o);
        if (threadIdx.x < 32) sh[threadIdx.x] = 0.f;
        __syncthreads();
        if (lane == 0) sh[warp_in_blk] = csum_local;
        __syncthreads();
        if (threadIdx.x < 32) {
            float v = sh[threadIdx.x];
            #pragma unroll
            for (int o = 16; o; o >>= 1) v += __shfl_down_sync(0xffffffffu, v, o);
            if (threadIdx.x == 0) atomicAdd(&g_Csum, v);
        }
    }
    grid_barrier();

    // ---------- Phase 2: edges pass 2 ----------
    {
        int e0 = tid, e1 = tid + nt;
        float f0 = __ldg(&ef[e0]);
        int   u0 = __ldg(&src[e0]);
        int   d0 = __ldg(&dst[e0]);
        bool has1 = (e1 < N_EDGES);
        float f1 = 0.f; int u1 = 0, d1 = 0;
        if (has1) { f1 = __ldg(&ef[e1]); u1 = __ldg(&src[e1]); d1 = __ldg(&dst[e1]); }
        float ow0 = g_outw[d0];
        float ow1 = has1 ? g_outw[d1] : 0.f;
        atomicAdd(&g_q[u0], edge_w(f0) * (1.0f + ow0));
        if (has1) atomicAdd(&g_q[u1], edge_w(f1) * (1.0f + ow1));
    }
    grid_barrier();

    // ---------- Phase 3: column sums, contiguous rows, unroll 8 ----------
    {
        const int sub = threadIdx.x / CSLICES;                 // 0..1
        const int t   = threadIdx.x - sub * CSLICES;           // 0..319
        const int lo  = (int)(((long)blockIdx.x * N_NODES) / gridDim.x);
        const int hi  = (int)(((long)(blockIdx.x + 1) * N_NODES) / gridDim.x);
        const float4* __restrict__ h4 = (const float4*)node;
        float4 aw = make_float4(0.f, 0.f, 0.f, 0.f);
        float4 as = make_float4(0.f, 0.f, 0.f, 0.f);
        int s = lo + sub;                                      // rows interleaved by 2
        for (; s + 14 < hi; s += 16) {
            float c[8]; float4 v[8];
            #pragma unroll
            for (int k = 0; k < 8; k++) {
                int r = s + 2 * k;
                c[k] = 1.0f + __ldg(&g_outw[r]) + __ldg(&g_q[r]);
            }
            #pragma unroll
            for (int k = 0; k < 8; k++) {
                int r = s + 2 * k;
                v[k] = __ldg(&h4[(long)r * D4 + t]);
            }
            #pragma unroll
            for (int k = 0; k < 8; k++) { fma4(aw, c[k], v[k]); add4(as, v[k]); }
        }
        for (; s < hi; s += 2) {
            float c = 1.0f + __ldg(&g_outw[s]) + __ldg(&g_q[s]);
            float4 v = __ldg(&h4[(long)s * D4 + t]);
            fma4(aw, c, v); add4(as, v);
        }
        // block-level shared reduction
        for (int i = threadIdx.x; i < DIM; i += blockDim.x) { s1sh[i] = 0.f; mssh[i] = 0.f; }
        __syncthreads();
        int d = 4 * t;
        atomicAdd(&s1sh[d + 0], aw.x); atomicAdd(&s1sh[d + 1], aw.y);
        atomicAdd(&s1sh[d + 2], aw.z); atomicAdd(&s1sh[d + 3], aw.w);
        atomicAdd(&mssh[d + 0], as.x); atomicAdd(&mssh[d + 1], as.y);
        atomicAdd(&mssh[d + 2], as.z); atomicAdd(&mssh[d + 3], as.w);
        __syncthreads();
        // banked global flush (contention /8)
        const int bank = blockIdx.x & (BANKS - 1);
        if (threadIdx.x < CSLICES) {
            float4 v = ((const float4*)s1sh)[threadIdx.x];
            float* dstp = &g_S1B[bank][4 * threadIdx.x];
            atomicAdd(dstp + 0, v.x); atomicAdd(dstp + 1, v.y);
            atomicAdd(dstp + 2, v.z); atomicAdd(dstp + 3, v.w);
        } else {
            int j = threadIdx.x - CSLICES;
            float4 v = ((const float4*)mssh)[j];
            float* dstp = &g_msumB[bank][4 * j];
            atomicAdd(dstp + 0, v.x); atomicAdd(dstp + 1, v.y);
            atomicAdd(dstp + 2, v.z); atomicAdd(dstp + 3, v.w);
        }
    }
    grid_barrier();

    // ---------- Phase 4: bank-sum S1 -> shared, v1 += partial ; reset outw/q ----------
    {
        const float invN = 1.0f / (float)N_NODES;
        const float C = (float)N_NODES + g_Csum;
        for (int i = threadIdx.x; i < DIM; i += blockDim.x) {
            float v = 0.f;
            #pragma unroll
            for (int b = 0; b < BANKS; b++) v += g_S1B[b][i];
            s1sh[i] = v * invN;                                // fold 1/N here
        }
        __syncthreads();
        if (row_mv < DIM) {
            const float4* __restrict__ wr = (const float4*)(W1 + (long)row_mv * DIM);
            const float4* __restrict__ s1 = (const float4*)s1sh;
            const int base = half_mv * (D4 / 2) + lane;
            float acc = 0.f;
            #pragma unroll
            for (int k = 0; k < 5; k++) {
                int j = base + k * 32;
                acc += dot4(__ldg(&wr[j]), s1[j]);
            }
            #pragma unroll
            for (int o = 16; o; o >>= 1) acc += __shfl_down_sync(0xffffffffu, acc, o);
            if (lane == 0) {
                float contrib = acc;
                if (half_mv == 0) contrib += C * invN * __ldg(&b1[row_mv]);
                atomicAdd(&g_v1[row_mv], contrib);
            }
        }
        for (int s2 = tid; s2 < N_NODES; s2 += nt) { g_outw[s2] = 0.f; g_q[s2] = 0.f; }
    }
    grid_barrier();

    // ---------- Phase 5: out += partial + b2 + msum/N ; reset Csum ----------
    {
        const float invN = 1.0f / (float)N_NODES;
        if (row_mv < DIM) {
            const float4* __restrict__ wr = (const float4*)(W2 + (long)row_mv * DIM);
            const float4* __restrict__ v1 = (const float4*)g_v1;
            const int base = half_mv * (D4 / 2) + lane;
            float acc = 0.f;
            #pragma unroll
            for (int k = 0; k < 5; k++) {
                int j = base + k * 32;
                acc += dot4(__ldg(&wr[j]), v1[j]);
            }
            #pragma unroll
            for (int o = 16; o; o >>= 1) acc += __shfl_down_sync(0xffffffffu, acc, o);
            if (lane == 0) {
                float contrib = acc;
                if (half_mv == 0) {
                    float ms = 0.f;
                    #pragma unroll
                    for (int b = 0; b < BANKS; b++) ms += g_msumB[b][row_mv];
                    contrib += __ldg(&b2[row_mv]) + ms * invN;
                }
                atomicAdd(&out[row_mv], contrib);
            }
        }
        if (tid == 0) g_Csum = 0.f;
    }
}

extern "C" void kernel_launch(void* const* d_in, const int* in_sizes, int n_in,
                              void* d_out, int out_size) {
    const float* node = (const float*)d_in[0];
    const float* ef   = (const float*)d_in[1];
    const int*   ei   = (const int*)  d_in[2];
    const float* W1   = (const float*)d_in[3];
    const float* b1   = (const float*)d_in[4];
    const float* W2   = (const float*)d_in[5];
    const float* b2   = (const float*)d_in[6];
    float* out = (float*)d_out;

    const int* src = ei;
    const int* dst = ei + N_EDGES;

    int dev = 0, sms = 148, maxb = 1;
    cudaGetDevice(&dev);
    cudaDeviceGetAttribute(&sms, cudaDevAttrMultiProcessorCount, dev);
    cudaOccupancyMaxActiveBlocksPerMultiprocessor(&maxb, fused_kernel, NTHREADS, 0);
    int grid = (maxb >= 1) ? sms : 1;
    if (grid < 1) grid = 1;

    fused_kernel<<<grid, NTHREADS>>>(node, ef, src, dst, W1, b1, W2, b2, out);
}